// round 15
// baseline (speedup 1.0000x reference)
#include <cuda_runtime.h>
#include <cuda_fp16.h>
#include <cstdint>

// Fixed shape: B=8, S=4096, H=1024
#define BDIM 8
#define SDIM 4096
#define HDIM 1024

// GEMM tiling (single-pass fp16)
#define BM 128
#define BN 64
#define BKH 32
#define KT (HDIM / BKH)
#define ROWB 80
#define APLANE (BM * ROWB)              // 10240
#define BPLANE (BN * ROWB)              // 5120
#define STAGE_BYTES (APLANE + BPLANE)   // 15360
#define OFF_AH 0
#define OFF_BH APLANE
#define NSTAGE 3
#define SMEM_DYN (NSTAGE * STAGE_BYTES + 512)   // 46592 -> 3+ CTAs/SM

// rescore
#define MAXC 1024
#define RCH 64
#define RZ 4
#define EPS 0.0025f
#define WND (2.0f * EPS)

// ---------------- device scratch ----------------
__device__ int g_tokpos[BDIM * SDIM];
__device__ int g_slot[BDIM * SDIM];
__device__ int g_nkeep[BDIM];
__device__ int g_nzero[BDIM];
__device__ unsigned g_score[BDIM * SDIM];     // approx monotone
__device__ unsigned g_exact[BDIM * SDIM];     // exact monotone (candidates)
__device__ float g_thrA[BDIM];
__device__ int g_ccount[BDIM];
__device__ int g_cand[BDIM * MAXC];
__device__ __half g_Ahi[BDIM * SDIM * HDIM];
__device__ __half g_Bhi[HDIM * HDIM];

// ---------------- helpers ----------------
__device__ __forceinline__ uint32_t smem_u32(const void* p) {
    uint32_t a;
    asm("{ .reg .u64 t; cvta.to.shared.u64 t, %1; cvt.u32.u64 %0, t; }" : "=r"(a) : "l"(p));
    return a;
}
#define CP16(d, s) asm volatile("cp.async.cg.shared.global [%0], [%1], 16;" :: "r"(d), "l"(s))
#define CP_COMMIT() asm volatile("cp.async.commit_group;" ::: "memory")
#define CP_WAIT1() asm volatile("cp.async.wait_group 1;" ::: "memory")
#define LDX4(R, addr) \
    asm volatile("ldmatrix.sync.aligned.m8n8.x4.shared.b16 {%0,%1,%2,%3}, [%4];" \
        : "=r"((R)[0]), "=r"((R)[1]), "=r"((R)[2]), "=r"((R)[3]) : "r"(addr))
#define MMA16816(C, A, B0, B1) \
    asm volatile("mma.sync.aligned.m16n8k16.row.col.f32.f16.f16.f32 " \
        "{%0,%1,%2,%3}, {%4,%5,%6,%7}, {%8,%9}, {%0,%1,%2,%3};" \
        : "+f"((C)[0]), "+f"((C)[1]), "+f"((C)[2]), "+f"((C)[3]) \
        : "r"((A)[0]), "r"((A)[1]), "r"((A)[2]), "r"((A)[3]), "r"(B0), "r"(B1))

__device__ __forceinline__ unsigned mono(float s) {
    unsigned u = __float_as_uint(s);
    return (u & 0x80000000u) ? ~u : (u | 0x80000000u);
}
__device__ __forceinline__ float unmono(unsigned u) {
    unsigned bits = (u & 0x80000000u) ? (u & 0x7FFFFFFFu) : ~u;
    return __uint_as_float(bits);
}
__device__ __forceinline__ float make_score(int base, int i, const float* amask) {
    float sc = unmono(g_score[base + i]);
    float a = amask[base + i];
    return sc + a * 100.0f + a;
}

// ---------------------------------------------------------------------------
// K1: compaction + counts + resets
// ---------------------------------------------------------------------------
__global__ void compact_kernel(const float* __restrict__ pmask,
                               const float* __restrict__ amask) {
    int b = blockIdx.x, t = threadIdx.x;
    __shared__ int cnt[1024];
    __shared__ int cntz_s[1024];
    int base = b * SDIM;
    int flags = 0, local = 0, localz = 0;
#pragma unroll
    for (int r = 0; r < 4; r++) {
        int p = t * 4 + r;
        bool k = pmask[base + p] > 0.5f;
        flags |= (int)k << r;
        local += k;
        if (k && amask[base + p] == 0.0f) localz++;
        g_score[base + p] = 0u;
        g_exact[base + p] = 0u;
        g_slot[base + p] = -1;
    }
    cnt[t] = local;
    cntz_s[t] = localz;
    __syncthreads();
    for (int off = 1; off < 1024; off <<= 1) {
        int v = (t >= off) ? cnt[t - off] : 0;
        int vz = (t >= off) ? cntz_s[t - off] : 0;
        __syncthreads();
        cnt[t] += v;
        cntz_s[t] += vz;
        __syncthreads();
    }
    int offset = cnt[t] - local;
#pragma unroll
    for (int r = 0; r < 4; r++) {
        if ((flags >> r) & 1) {
            g_tokpos[base + offset] = t * 4 + r;
            g_slot[base + t * 4 + r] = offset;
            offset++;
        }
    }
    if (t == 1023) {
        g_nkeep[b] = cnt[1023];
        g_nzero[b] = cntz_s[1023];
    }
}

// ---------------------------------------------------------------------------
// K_prepW: W[k][n] -> W^T[n][k] fp16 (hi only)
// ---------------------------------------------------------------------------
__global__ void prep_w(const float* __restrict__ W) {
    __shared__ float t[32][33];
    int n0 = blockIdx.x * 32, k0 = blockIdx.y * 32;
    int tx = threadIdx.x, ty = threadIdx.y;
#pragma unroll
    for (int r = 0; r < 4; r++)
        t[ty + r * 8][tx] = W[(size_t)(k0 + ty + r * 8) * HDIM + n0 + tx];
    __syncthreads();
#pragma unroll
    for (int r = 0; r < 4; r++) {
        int n = ty + r * 8;
        g_Bhi[(size_t)(n0 + n) * HDIM + k0 + tx] = __float2half_rn(t[tx][n]);
    }
}

// ---------------------------------------------------------------------------
// K_prep_copy: copy hidden->out_ret; kept rows -> fp16 hi compacted plane
// ---------------------------------------------------------------------------
__global__ void prep_copy(const float4* __restrict__ hid, float4* __restrict__ out_ret) {
    int row = blockIdx.x;
    const float4* src = hid + (size_t)row * (HDIM / 4);
    float4* dst = out_ret + (size_t)row * (HDIM / 4);
    int slot = g_slot[row];
    if (slot < 0) {
#pragma unroll
        for (int i = 0; i < 2; i++) {
            int e4 = threadIdx.x + i * 128;
            dst[e4] = src[e4];
        }
        return;
    }
    int b = row >> 12;
    size_t dbase = (size_t)((b << 12) + slot) * HDIM;
#pragma unroll
    for (int i = 0; i < 2; i++) {
        int e4 = threadIdx.x + i * 128;
        float4 v = src[e4];
        dst[e4] = v;
        __half h0 = __float2half_rn(v.x), h1 = __float2half_rn(v.y);
        __half h2 = __float2half_rn(v.z), h3 = __float2half_rn(v.w);
        uint2 uh;
        uh.x = ((unsigned)__half_as_ushort(h1) << 16) | __half_as_ushort(h0);
        uh.y = ((unsigned)__half_as_ushort(h3) << 16) | __half_as_ushort(h2);
        *(uint2*)(g_Ahi + dbase + e4 * 4) = uh;
    }
}

// ---------------------------------------------------------------------------
// K2: single-pass fp16 GEMM, row-max epilogue -> approx g_score
// ---------------------------------------------------------------------------
__global__ void __launch_bounds__(256, 3)
score_gemm(const float* __restrict__ bias) {
    int b = blockIdx.z;
    int nk = g_nkeep[b];
    int m0 = blockIdx.x * BM;
    if (m0 >= nk) return;
    int n0 = blockIdx.y * BN;

    extern __shared__ __align__(128) char sm[];
    uint32_t sb = smem_u32(sm);
    float* biasS = (float*)(sm + NSTAGE * STAGE_BYTES);

    int tid = threadIdx.x, wid = tid >> 5, lane = tid & 31;
    if (tid < BN) biasS[tid] = bias[n0 + tid];

    const __half* gah = g_Ahi + (size_t)(b * SDIM + m0) * HDIM;
    const __half* gbh = g_Bhi + (size_t)n0 * HDIM;

#define LOAD_STAGE(s, k0)                                                     \
    do {                                                                      \
        uint32_t st_ = sb + (s) * STAGE_BYTES;                                \
        _Pragma("unroll")                                                     \
        for (int i_ = 0; i_ < 2; i_++) {                                      \
            int cid_ = tid + i_ * 256;                                        \
            int r_ = cid_ >> 2, c_ = cid_ & 3;                                \
            uint32_t so_ = (uint32_t)(r_ * ROWB + c_ * 16);                   \
            size_t go_ = (size_t)r_ * HDIM + (k0) + c_ * 8;                   \
            CP16(st_ + OFF_AH + so_, gah + go_);                              \
        }                                                                     \
        {                                                                     \
            int r_ = tid >> 2, c_ = tid & 3;                                  \
            uint32_t so_ = (uint32_t)(r_ * ROWB + c_ * 16);                   \
            size_t go_ = (size_t)r_ * HDIM + (k0) + c_ * 8;                   \
            CP16(st_ + OFF_BH + so_, gbh + go_);                              \
        }                                                                     \
    } while (0)

    LOAD_STAGE(0, 0);
    CP_COMMIT();
    LOAD_STAGE(1, BKH);
    CP_COMMIT();

    int wm = wid >> 1, wn = wid & 1;
    float acc[2][4][4];
#pragma unroll
    for (int mt = 0; mt < 2; mt++)
#pragma unroll
        for (int nt = 0; nt < 4; nt++)
#pragma unroll
            for (int e = 0; e < 4; e++) acc[mt][nt][e] = 0.0f;

    uint32_t arow = (uint32_t)(wm * 32 + (lane & 15));
    uint32_t brow = (uint32_t)(wn * 32 + (lane & 15));
    uint32_t kcol = (uint32_t)((lane >> 4) * 16);

    int stage = 0;
    for (int kt = 0; kt < KT; kt++) {
        CP_WAIT1();
        __syncthreads();
        if (kt + 2 < KT) {
            int ns = stage + 2;
            if (ns >= NSTAGE) ns -= NSTAGE;
            LOAD_STAGE(ns, (kt + 2) * BKH);
        }
        CP_COMMIT();

        uint32_t st = sb + stage * STAGE_BYTES;
#pragma unroll
        for (int ks = 0; ks < 2; ks++) {
            uint32_t koff = (uint32_t)(ks * 32) + kcol;
            uint32_t ah[2][4], bh2[2][4];
#pragma unroll
            for (int g = 0; g < 2; g++)
                LDX4(bh2[g], st + OFF_BH + (brow + g * 16) * ROWB + koff);
#pragma unroll
            for (int mt = 0; mt < 2; mt++)
                LDX4(ah[mt], st + OFF_AH + (arow + mt * 16) * ROWB + koff);
#pragma unroll
            for (int mt = 0; mt < 2; mt++)
#pragma unroll
                for (int nt = 0; nt < 4; nt++) {
                    int g = nt >> 1, s2 = nt & 1;
                    MMA16816(acc[mt][nt], ah[mt], bh2[g][s2], bh2[g][s2 + 2]);
                }
        }
        stage++;
        if (stage >= NSTAGE) stage = 0;
    }

    float rmax[2][2];
#pragma unroll
    for (int mt = 0; mt < 2; mt++) { rmax[mt][0] = -3.4e38f; rmax[mt][1] = -3.4e38f; }
#pragma unroll
    for (int mt = 0; mt < 2; mt++)
#pragma unroll
        for (int nt = 0; nt < 4; nt++) {
            int cb = wn * 32 + nt * 8 + (lane & 3) * 2;
            float b0 = biasS[cb], b1 = biasS[cb + 1];
            rmax[mt][0] = fmaxf(rmax[mt][0], fmaxf(acc[mt][nt][0] + b0, acc[mt][nt][1] + b1));
            rmax[mt][1] = fmaxf(rmax[mt][1], fmaxf(acc[mt][nt][2] + b0, acc[mt][nt][3] + b1));
        }
#pragma unroll
    for (int off = 1; off <= 2; off <<= 1)
#pragma unroll
        for (int mt = 0; mt < 2; mt++) {
            rmax[mt][0] = fmaxf(rmax[mt][0], __shfl_xor_sync(0xFFFFFFFFu, rmax[mt][0], off));
            rmax[mt][1] = fmaxf(rmax[mt][1], __shfl_xor_sync(0xFFFFFFFFu, rmax[mt][1], off));
        }
    if ((lane & 3) == 0) {
#pragma unroll
        for (int mt = 0; mt < 2; mt++)
#pragma unroll
            for (int h2 = 0; h2 < 2; h2++) {
                int m = m0 + wm * 32 + mt * 16 + (lane >> 2) + h2 * 8;
                if (m < nk) {
                    int pos = g_tokpos[b * SDIM + m];
                    atomicMax(&g_score[b * SDIM + pos], mono(rmax[mt][h2]));
                }
            }
    }
#undef LOAD_STAGE
}

// ---------------------------------------------------------------------------
// K3: radix/histogram select of T-th largest approx score -> thrA,
// then collect boundary candidates. Replaces the 4096-u64 bitonic sort.
// ---------------------------------------------------------------------------
__global__ void select1_kernel(const float* __restrict__ pmask,
                               const float* __restrict__ amask) {
    int b = blockIdx.x, t = threadIdx.x;
    __shared__ unsigned hist[256];
    __shared__ unsigned sfx[257];
    __shared__ unsigned prefix_s;
    __shared__ int remaining_s;
    __shared__ int cb_s;
    int base = b * SDIM;

    // load scores once into registers
    float sc[4];
    unsigned v[4];
    bool keep[4];
#pragma unroll
    for (int r = 0; r < 4; r++) {
        int i = t * 4 + r;
        keep[r] = pmask[base + i] > 0.5f;
        sc[r] = keep[r] ? make_score(base, i, amask) : 0.0f;
        v[r] = mono(sc[r]);
    }

    if (t == 0) {
        int T = (int)((float)g_nzero[b] * 0.8f);
        if (T < 1) T = 1;
        remaining_s = T;
        prefix_s = 0u;
        g_ccount[b] = 0;
    }
    __syncthreads();

    for (int level = 0; level < 4; level++) {
        int shift = 24 - 8 * level;
        unsigned himask = (level == 0) ? 0u : (~0u << (shift + 8));
        unsigned prefix = prefix_s;
        int remaining = remaining_s;
        if (t < 256) hist[t] = 0u;
        __syncthreads();
#pragma unroll
        for (int r = 0; r < 4; r++)
            if (keep[r] && (v[r] & himask) == prefix)
                atomicAdd(&hist[(v[r] >> shift) & 255u], 1u);
        __syncthreads();
        // suffix sums via one warp (lane l owns bins [l*8, l*8+8))
        if (t < 32) {
            unsigned h[8], gsum = 0;
#pragma unroll
            for (int q = 0; q < 8; q++) { h[q] = hist[t * 8 + q]; gsum += h[q]; }
            unsigned incl = gsum;
#pragma unroll
            for (int off = 1; off < 32; off <<= 1) {
                unsigned o = __shfl_down_sync(0xFFFFFFFFu, incl, off);
                if (t + off < 32) incl += o;
            }
            unsigned run = incl - gsum;   // groups above
#pragma unroll
            for (int q = 7; q >= 0; q--) { run += h[q]; sfx[t * 8 + q] = run; }
            if (t == 0) sfx[256] = 0u;
        }
        __syncthreads();
        // pick bucket: unique j with sfx[j] >= remaining > sfx[j+1]
        if (t < 256) {
            if ((int)sfx[t] >= remaining && (int)sfx[t + 1] < remaining) cb_s = t;
        }
        __syncthreads();
        if (t == 0) {
            int cb = cb_s;
            remaining_s = remaining - (int)sfx[cb + 1];
            prefix_s = prefix | ((unsigned)cb << shift);
        }
        __syncthreads();
    }

    unsigned thrU = prefix_s;
    float thr = unmono(thrU);
    if (t == 0) g_thrA[b] = thr;

    // candidate collection (same band as before)
#pragma unroll
    for (int r = 0; r < 4; r++) {
        if (keep[r] && fabsf(sc[r] - thr) <= WND) {
            int idx = atomicAdd(&g_ccount[b], 1);
            if (idx < MAXC) g_cand[b * MAXC + idx] = t * 4 + r;
        }
    }
}

// ---------------------------------------------------------------------------
// K4: exact fp32 rescore — register-blocked 4col x 8cand per thread,
// hs transposed [kk][cand], warp-local reduction; idle warps skip FMA.
// grid (8 ntile, BDIM, RZ), block 256
// ---------------------------------------------------------------------------
__global__ void __launch_bounds__(256)
rescore_kernel(const float* __restrict__ hid, const float* __restrict__ W,
               const float* __restrict__ bias) {
    int b = blockIdx.y, nt = blockIdx.x, zc = blockIdx.z;
    int C = g_ccount[b];
    if (C > MAXC) C = MAXC;
    if (C == 0) return;

    __shared__ float Ws[32][128];
    __shared__ __align__(16) float hs[32][RCH];
    __shared__ int cpos[RCH];

    int tid = threadIdx.x;
    int ct = tid & 31;
    int cg = tid >> 5;
    int n0 = nt * 128;
    float bv[4];
#pragma unroll
    for (int q = 0; q < 4; q++) bv[q] = bias[n0 + ct + 32 * q];

    for (int c0 = zc * RCH; c0 < C; c0 += RZ * RCH) {
        int nc = C - c0;
        if (nc > RCH) nc = RCH;
        __syncthreads();
        if (tid < nc) cpos[tid] = g_cand[b * MAXC + c0 + tid];

        float acc[4][8];
#pragma unroll
        for (int q = 0; q < 4; q++)
#pragma unroll
            for (int j = 0; j < 8; j++) acc[q][j] = 0.0f;

        bool active = (cg * 8 < nc);

        for (int kt = 0; kt < 32; kt++) {
            __syncthreads();
            for (int i = tid; i < 4096; i += 256) {
                int kk = i >> 7, nn = i & 127;
                Ws[kk][nn] = W[(size_t)(kt * 32 + kk) * HDIM + n0 + nn];
            }
            for (int i = tid; i < 32 * RCH; i += 256) {
                int kk = i >> 6, c = i & 63;
                hs[kk][c] = (c < nc)
                    ? hid[(size_t)(b * SDIM + cpos[c]) * HDIM + kt * 32 + kk]
                    : 0.0f;
            }
            __syncthreads();
            if (active) {
#pragma unroll 4
                for (int kk = 0; kk < 32; kk++) {
                    float w0 = Ws[kk][ct], w1 = Ws[kk][ct + 32];
                    float w2 = Ws[kk][ct + 64], w3 = Ws[kk][ct + 96];
                    float4 ha = *(const float4*)&hs[kk][cg * 8];
                    float4 hb = *(const float4*)&hs[kk][cg * 8 + 4];
                    float h[8] = {ha.x, ha.y, ha.z, ha.w, hb.x, hb.y, hb.z, hb.w};
#pragma unroll
                    for (int j = 0; j < 8; j++) {
                        acc[0][j] += w0 * h[j];
                        acc[1][j] += w1 * h[j];
                        acc[2][j] += w2 * h[j];
                        acc[3][j] += w3 * h[j];
                    }
                }
            }
        }
        if (active) {
#pragma unroll
            for (int j = 0; j < 8; j++) {
                float v = fmaxf(fmaxf(acc[0][j] + bv[0], acc[1][j] + bv[1]),
                                fmaxf(acc[2][j] + bv[2], acc[3][j] + bv[3]));
#pragma unroll
                for (int off = 16; off > 0; off >>= 1)
                    v = fmaxf(v, __shfl_xor_sync(0xFFFFFFFFu, v, off));
                int c = cg * 8 + j;
                if (ct == 0 && c < nc)
                    atomicMax(&g_exact[b * SDIM + cpos[c]], mono(v));
            }
        }
    }
}

// ---------------------------------------------------------------------------
// K5: final classification -> mask (runtime-sized candidate sort)
// ---------------------------------------------------------------------------
__global__ void select2_kernel(const float* __restrict__ pmask,
                               const float* __restrict__ amask,
                               float* __restrict__ outmask) {
    int b = blockIdx.x, t = threadIdx.x;
    __shared__ unsigned long long ck[MAXC];
    __shared__ int cnt[1024];
    __shared__ unsigned long long cthrS;
    int base = b * SDIM;
    float thr = g_thrA[b];
    int C = g_ccount[b];
    if (C > MAXC) C = MAXC;

    int psize = 1;
    while (psize < C) psize <<= 1;
    if (psize < 2) psize = 2;

    int local = 0;
#pragma unroll
    for (int r = 0; r < 4; r++) {
        int i = t * 4 + r;
        if (pmask[base + i] > 0.5f && make_score(base, i, amask) > thr + WND) local++;
    }
    cnt[t] = local;

    if (t < psize) {
        unsigned long long myk = 0ull;
        if (t < C) {
            int pos = g_cand[b * MAXC + t];
            myk = ((unsigned long long)g_exact[base + pos] << 32) |
                  (unsigned long long)(0xFFFFFFFFu - (unsigned)pos);
        }
        ck[t] = myk;
    }
    __syncthreads();

    for (int off = 512; off > 0; off >>= 1) {
        if (t < off) cnt[t] += cnt[t + off];
        __syncthreads();
    }
    int D = cnt[0];

    // bitonic sort over psize entries (all threads hit the barriers)
    for (int k = 2; k <= psize; k <<= 1)
        for (int j = k >> 1; j > 0; j >>= 1) {
            int ixj = t ^ j;
            if (t < psize && ixj > t) {
                unsigned long long A = ck[t], B = ck[ixj];
                bool up = ((t & k) == 0);
                if ((A > B) == up) { ck[t] = B; ck[ixj] = A; }
            }
            __syncthreads();
        }

    if (t == 0) {
        int T = (int)((float)g_nzero[b] * 0.8f);
        if (T < 1) T = 1;
        int r = T - D;
        if (r < 1) cthrS = ~0ull;
        else {
            if (r > C) r = C;
            cthrS = ck[psize - r];
        }
    }
    __syncthreads();
    unsigned long long cthr = cthrS;

#pragma unroll
    for (int r = 0; r < 4; r++) {
        int i = t * 4 + r;
        float out = 0.0f;
        if (pmask[base + i] > 0.5f) {
            float sc = make_score(base, i, amask);
            if (sc > thr + WND) out = 1.0f;
            else if (fabsf(sc - thr) <= WND) {
                unsigned long long k = ((unsigned long long)g_exact[base + i] << 32) |
                                       (unsigned long long)(0xFFFFFFFFu - (unsigned)i);
                if (k >= cthr) out = 1.0f;
            }
        }
        outmask[base + i] = out;
    }
}

// ---------------------------------------------------------------------------
extern "C" void kernel_launch(void* const* d_in, const int* in_sizes, int n_in,
                              void* d_out, int out_size) {
    const float* hidden = (const float*)d_in[0];
    const float* amask  = (const float*)d_in[1];
    const float* pmask  = (const float*)d_in[2];
    const float* W      = (const float*)d_in[3];
    const float* bias   = (const float*)d_in[4];
    float* out = (float*)d_out;

    const int nh = BDIM * SDIM * HDIM;
    float* out_ret  = out;
    float* out_mask = out + nh;

    cudaFuncSetAttribute(score_gemm, cudaFuncAttributeMaxDynamicSharedMemorySize, SMEM_DYN);

    compact_kernel<<<BDIM, 1024>>>(pmask, amask);
    prep_w<<<dim3(32, 32), dim3(32, 8)>>>(W);
    prep_copy<<<BDIM * SDIM, 128>>>((const float4*)hidden, (float4*)out_ret);
    score_gemm<<<dim3(SDIM / BM, HDIM / BN, BDIM), 256, SMEM_DYN>>>(bias);
    select1_kernel<<<BDIM, 1024>>>(pmask, amask);
    rescore_kernel<<<dim3(8, BDIM, RZ), 256>>>(hidden, W, bias);
    select2_kernel<<<BDIM, 1024>>>(pmask, amask, out_mask);
}

// round 16
// speedup vs baseline: 1.4119x; 1.4119x over previous
#include <cuda_runtime.h>
#include <cuda_fp16.h>
#include <cstdint>

// Fixed shape: B=8, S=4096, H=1024
#define BDIM 8
#define SDIM 4096
#define HDIM 1024

// GEMM tiling (single-pass fp16)
#define BM 128
#define BN 64
#define BKH 32
#define KT (HDIM / BKH)
#define ROWB 80
#define APLANE (BM * ROWB)              // 10240
#define BPLANE (BN * ROWB)              // 5120
#define STAGE_BYTES (APLANE + BPLANE)   // 15360
#define OFF_AH 0
#define OFF_BH APLANE
#define NSTAGE 3
#define SMEM_DYN (NSTAGE * STAGE_BYTES + 512)   // 46592 -> 3+ CTAs/SM

// rescore
#define MAXC 1024
#define RCH 64
#define RZ 4
#define EPS 0.0025f
#define WND (2.0f * EPS)

// ---------------- device scratch ----------------
__device__ int g_tokpos[BDIM * SDIM];
__device__ int g_slot[BDIM * SDIM];
__device__ int g_nkeep[BDIM];
__device__ int g_nzero[BDIM];
__device__ unsigned g_score[BDIM * SDIM];     // approx monotone
__device__ unsigned g_exact[BDIM * SDIM];     // exact monotone (candidates)
__device__ float g_thrA[BDIM];
__device__ int g_ccount[BDIM];
__device__ int g_cand[BDIM * MAXC];
__device__ __half g_Ahi[BDIM * SDIM * HDIM];
__device__ __half g_Bhi[HDIM * HDIM];

// ---------------- helpers ----------------
__device__ __forceinline__ uint32_t smem_u32(const void* p) {
    uint32_t a;
    asm("{ .reg .u64 t; cvta.to.shared.u64 t, %1; cvt.u32.u64 %0, t; }" : "=r"(a) : "l"(p));
    return a;
}
#define CP16(d, s) asm volatile("cp.async.cg.shared.global [%0], [%1], 16;" :: "r"(d), "l"(s))
#define CP_COMMIT() asm volatile("cp.async.commit_group;" ::: "memory")
#define CP_WAIT1() asm volatile("cp.async.wait_group 1;" ::: "memory")
#define LDX4(R, addr) \
    asm volatile("ldmatrix.sync.aligned.m8n8.x4.shared.b16 {%0,%1,%2,%3}, [%4];" \
        : "=r"((R)[0]), "=r"((R)[1]), "=r"((R)[2]), "=r"((R)[3]) : "r"(addr))
#define MMA16816(C, A, B0, B1) \
    asm volatile("mma.sync.aligned.m16n8k16.row.col.f32.f16.f16.f32 " \
        "{%0,%1,%2,%3}, {%4,%5,%6,%7}, {%8,%9}, {%0,%1,%2,%3};" \
        : "+f"((C)[0]), "+f"((C)[1]), "+f"((C)[2]), "+f"((C)[3]) \
        : "r"((A)[0]), "r"((A)[1]), "r"((A)[2]), "r"((A)[3]), "r"(B0), "r"(B1))

__device__ __forceinline__ unsigned mono(float s) {
    unsigned u = __float_as_uint(s);
    return (u & 0x80000000u) ? ~u : (u | 0x80000000u);
}
__device__ __forceinline__ float unmono(unsigned u) {
    unsigned bits = (u & 0x80000000u) ? (u & 0x7FFFFFFFu) : ~u;
    return __uint_as_float(bits);
}
__device__ __forceinline__ float make_score(int base, int i, const float* amask) {
    float sc = unmono(g_score[base + i]);
    float a = amask[base + i];
    return sc + a * 100.0f + a;
}

// ---------------------------------------------------------------------------
// K1: compaction + counts + resets
// ---------------------------------------------------------------------------
__global__ void compact_kernel(const float* __restrict__ pmask,
                               const float* __restrict__ amask) {
    int b = blockIdx.x, t = threadIdx.x;
    __shared__ int cnt[1024];
    __shared__ int cntz_s[1024];
    int base = b * SDIM;
    int flags = 0, local = 0, localz = 0;
#pragma unroll
    for (int r = 0; r < 4; r++) {
        int p = t * 4 + r;
        bool k = pmask[base + p] > 0.5f;
        flags |= (int)k << r;
        local += k;
        if (k && amask[base + p] == 0.0f) localz++;
        g_score[base + p] = 0u;
        g_exact[base + p] = 0u;
        g_slot[base + p] = -1;
    }
    cnt[t] = local;
    cntz_s[t] = localz;
    __syncthreads();
    for (int off = 1; off < 1024; off <<= 1) {
        int v = (t >= off) ? cnt[t - off] : 0;
        int vz = (t >= off) ? cntz_s[t - off] : 0;
        __syncthreads();
        cnt[t] += v;
        cntz_s[t] += vz;
        __syncthreads();
    }
    int offset = cnt[t] - local;
#pragma unroll
    for (int r = 0; r < 4; r++) {
        if ((flags >> r) & 1) {
            g_tokpos[base + offset] = t * 4 + r;
            g_slot[base + t * 4 + r] = offset;
            offset++;
        }
    }
    if (t == 1023) {
        g_nkeep[b] = cnt[1023];
        g_nzero[b] = cntz_s[1023];
    }
}

// ---------------------------------------------------------------------------
// K_prepW: W[k][n] -> W^T[n][k] fp16 (hi only)
// ---------------------------------------------------------------------------
__global__ void prep_w(const float* __restrict__ W) {
    __shared__ float t[32][33];
    int n0 = blockIdx.x * 32, k0 = blockIdx.y * 32;
    int tx = threadIdx.x, ty = threadIdx.y;
#pragma unroll
    for (int r = 0; r < 4; r++)
        t[ty + r * 8][tx] = W[(size_t)(k0 + ty + r * 8) * HDIM + n0 + tx];
    __syncthreads();
#pragma unroll
    for (int r = 0; r < 4; r++) {
        int n = ty + r * 8;
        g_Bhi[(size_t)(n0 + n) * HDIM + k0 + tx] = __float2half_rn(t[tx][n]);
    }
}

// ---------------------------------------------------------------------------
// K_prep_copy: copy hidden->out_ret; kept rows -> fp16 hi compacted plane
// ---------------------------------------------------------------------------
__global__ void prep_copy(const float4* __restrict__ hid, float4* __restrict__ out_ret) {
    int row = blockIdx.x;
    const float4* src = hid + (size_t)row * (HDIM / 4);
    float4* dst = out_ret + (size_t)row * (HDIM / 4);
    int slot = g_slot[row];
    if (slot < 0) {
#pragma unroll
        for (int i = 0; i < 2; i++) {
            int e4 = threadIdx.x + i * 128;
            dst[e4] = src[e4];
        }
        return;
    }
    int b = row >> 12;
    size_t dbase = (size_t)((b << 12) + slot) * HDIM;
#pragma unroll
    for (int i = 0; i < 2; i++) {
        int e4 = threadIdx.x + i * 128;
        float4 v = src[e4];
        dst[e4] = v;
        __half h0 = __float2half_rn(v.x), h1 = __float2half_rn(v.y);
        __half h2 = __float2half_rn(v.z), h3 = __float2half_rn(v.w);
        uint2 uh;
        uh.x = ((unsigned)__half_as_ushort(h1) << 16) | __half_as_ushort(h0);
        uh.y = ((unsigned)__half_as_ushort(h3) << 16) | __half_as_ushort(h2);
        *(uint2*)(g_Ahi + dbase + e4 * 4) = uh;
    }
}

// ---------------------------------------------------------------------------
// K2: single-pass fp16 GEMM, row-max epilogue -> approx g_score
// ---------------------------------------------------------------------------
__global__ void __launch_bounds__(256, 3)
score_gemm(const float* __restrict__ bias) {
    int b = blockIdx.z;
    int nk = g_nkeep[b];
    int m0 = blockIdx.x * BM;
    if (m0 >= nk) return;
    int n0 = blockIdx.y * BN;

    extern __shared__ __align__(128) char sm[];
    uint32_t sb = smem_u32(sm);
    float* biasS = (float*)(sm + NSTAGE * STAGE_BYTES);

    int tid = threadIdx.x, wid = tid >> 5, lane = tid & 31;
    if (tid < BN) biasS[tid] = bias[n0 + tid];

    const __half* gah = g_Ahi + (size_t)(b * SDIM + m0) * HDIM;
    const __half* gbh = g_Bhi + (size_t)n0 * HDIM;

#define LOAD_STAGE(s, k0)                                                     \
    do {                                                                      \
        uint32_t st_ = sb + (s) * STAGE_BYTES;                                \
        _Pragma("unroll")                                                     \
        for (int i_ = 0; i_ < 2; i_++) {                                      \
            int cid_ = tid + i_ * 256;                                        \
            int r_ = cid_ >> 2, c_ = cid_ & 3;                                \
            uint32_t so_ = (uint32_t)(r_ * ROWB + c_ * 16);                   \
            size_t go_ = (size_t)r_ * HDIM + (k0) + c_ * 8;                   \
            CP16(st_ + OFF_AH + so_, gah + go_);                              \
        }                                                                     \
        {                                                                     \
            int r_ = tid >> 2, c_ = tid & 3;                                  \
            uint32_t so_ = (uint32_t)(r_ * ROWB + c_ * 16);                   \
            size_t go_ = (size_t)r_ * HDIM + (k0) + c_ * 8;                   \
            CP16(st_ + OFF_BH + so_, gbh + go_);                              \
        }                                                                     \
    } while (0)

    LOAD_STAGE(0, 0);
    CP_COMMIT();
    LOAD_STAGE(1, BKH);
    CP_COMMIT();

    int wm = wid >> 1, wn = wid & 1;
    float acc[2][4][4];
#pragma unroll
    for (int mt = 0; mt < 2; mt++)
#pragma unroll
        for (int nt = 0; nt < 4; nt++)
#pragma unroll
            for (int e = 0; e < 4; e++) acc[mt][nt][e] = 0.0f;

    uint32_t arow = (uint32_t)(wm * 32 + (lane & 15));
    uint32_t brow = (uint32_t)(wn * 32 + (lane & 15));
    uint32_t kcol = (uint32_t)((lane >> 4) * 16);

    int stage = 0;
    for (int kt = 0; kt < KT; kt++) {
        CP_WAIT1();
        __syncthreads();
        if (kt + 2 < KT) {
            int ns = stage + 2;
            if (ns >= NSTAGE) ns -= NSTAGE;
            LOAD_STAGE(ns, (kt + 2) * BKH);
        }
        CP_COMMIT();

        uint32_t st = sb + stage * STAGE_BYTES;
#pragma unroll
        for (int ks = 0; ks < 2; ks++) {
            uint32_t koff = (uint32_t)(ks * 32) + kcol;
            uint32_t ah[2][4], bh2[2][4];
#pragma unroll
            for (int g = 0; g < 2; g++)
                LDX4(bh2[g], st + OFF_BH + (brow + g * 16) * ROWB + koff);
#pragma unroll
            for (int mt = 0; mt < 2; mt++)
                LDX4(ah[mt], st + OFF_AH + (arow + mt * 16) * ROWB + koff);
#pragma unroll
            for (int mt = 0; mt < 2; mt++)
#pragma unroll
                for (int nt = 0; nt < 4; nt++) {
                    int g = nt >> 1, s2 = nt & 1;
                    MMA16816(acc[mt][nt], ah[mt], bh2[g][s2], bh2[g][s2 + 2]);
                }
        }
        stage++;
        if (stage >= NSTAGE) stage = 0;
    }

    float rmax[2][2];
#pragma unroll
    for (int mt = 0; mt < 2; mt++) { rmax[mt][0] = -3.4e38f; rmax[mt][1] = -3.4e38f; }
#pragma unroll
    for (int mt = 0; mt < 2; mt++)
#pragma unroll
        for (int nt = 0; nt < 4; nt++) {
            int cb = wn * 32 + nt * 8 + (lane & 3) * 2;
            float b0 = biasS[cb], b1 = biasS[cb + 1];
            rmax[mt][0] = fmaxf(rmax[mt][0], fmaxf(acc[mt][nt][0] + b0, acc[mt][nt][1] + b1));
            rmax[mt][1] = fmaxf(rmax[mt][1], fmaxf(acc[mt][nt][2] + b0, acc[mt][nt][3] + b1));
        }
#pragma unroll
    for (int off = 1; off <= 2; off <<= 1)
#pragma unroll
        for (int mt = 0; mt < 2; mt++) {
            rmax[mt][0] = fmaxf(rmax[mt][0], __shfl_xor_sync(0xFFFFFFFFu, rmax[mt][0], off));
            rmax[mt][1] = fmaxf(rmax[mt][1], __shfl_xor_sync(0xFFFFFFFFu, rmax[mt][1], off));
        }
    if ((lane & 3) == 0) {
#pragma unroll
        for (int mt = 0; mt < 2; mt++)
#pragma unroll
            for (int h2 = 0; h2 < 2; h2++) {
                int m = m0 + wm * 32 + mt * 16 + (lane >> 2) + h2 * 8;
                if (m < nk) {
                    int pos = g_tokpos[b * SDIM + m];
                    atomicMax(&g_score[b * SDIM + pos], mono(rmax[mt][h2]));
                }
            }
    }
#undef LOAD_STAGE
}

// ---------------------------------------------------------------------------
// K3: radix/histogram select of T-th largest approx score -> thrA,
// then collect boundary candidates.
// ---------------------------------------------------------------------------
__global__ void select1_kernel(const float* __restrict__ pmask,
                               const float* __restrict__ amask) {
    int b = blockIdx.x, t = threadIdx.x;
    __shared__ unsigned hist[256];
    __shared__ unsigned sfx[257];
    __shared__ unsigned prefix_s;
    __shared__ int remaining_s;
    __shared__ int cb_s;
    int base = b * SDIM;

    float sc[4];
    unsigned v[4];
    bool keep[4];
#pragma unroll
    for (int r = 0; r < 4; r++) {
        int i = t * 4 + r;
        keep[r] = pmask[base + i] > 0.5f;
        sc[r] = keep[r] ? make_score(base, i, amask) : 0.0f;
        v[r] = mono(sc[r]);
    }

    if (t == 0) {
        int T = (int)((float)g_nzero[b] * 0.8f);
        if (T < 1) T = 1;
        remaining_s = T;
        prefix_s = 0u;
        g_ccount[b] = 0;
    }
    __syncthreads();

    for (int level = 0; level < 4; level++) {
        int shift = 24 - 8 * level;
        unsigned himask = (level == 0) ? 0u : (~0u << (shift + 8));
        unsigned prefix = prefix_s;
        int remaining = remaining_s;
        if (t < 256) hist[t] = 0u;
        __syncthreads();
#pragma unroll
        for (int r = 0; r < 4; r++)
            if (keep[r] && (v[r] & himask) == prefix)
                atomicAdd(&hist[(v[r] >> shift) & 255u], 1u);
        __syncthreads();
        if (t < 32) {
            unsigned h[8], gsum = 0;
#pragma unroll
            for (int q = 0; q < 8; q++) { h[q] = hist[t * 8 + q]; gsum += h[q]; }
            unsigned incl = gsum;
#pragma unroll
            for (int off = 1; off < 32; off <<= 1) {
                unsigned o = __shfl_down_sync(0xFFFFFFFFu, incl, off);
                if (t + off < 32) incl += o;
            }
            unsigned run = incl - gsum;
#pragma unroll
            for (int q = 7; q >= 0; q--) { run += h[q]; sfx[t * 8 + q] = run; }
            if (t == 0) sfx[256] = 0u;
        }
        __syncthreads();
        if (t < 256) {
            if ((int)sfx[t] >= remaining && (int)sfx[t + 1] < remaining) cb_s = t;
        }
        __syncthreads();
        if (t == 0) {
            int cb = cb_s;
            remaining_s = remaining - (int)sfx[cb + 1];
            prefix_s = prefix | ((unsigned)cb << shift);
        }
        __syncthreads();
    }

    unsigned thrU = prefix_s;
    float thr = unmono(thrU);
    if (t == 0) g_thrA[b] = thr;

#pragma unroll
    for (int r = 0; r < 4; r++) {
        if (keep[r] && fabsf(sc[r] - thr) <= WND) {
            int idx = atomicAdd(&g_ccount[b], 1);
            if (idx < MAXC) g_cand[b * MAXC + idx] = t * 4 + r;
        }
    }
}

// ---------------------------------------------------------------------------
// K4: exact fp32 rescore — register-blocked 4col x 8cand per thread,
// hs transposed [kk][cand], warp-local reduction; idle warps skip FMA.
// ---------------------------------------------------------------------------
__global__ void __launch_bounds__(256)
rescore_kernel(const float* __restrict__ hid, const float* __restrict__ W,
               const float* __restrict__ bias) {
    int b = blockIdx.y, nt = blockIdx.x, zc = blockIdx.z;
    int C = g_ccount[b];
    if (C > MAXC) C = MAXC;
    if (C == 0) return;

    __shared__ float Ws[32][128];
    __shared__ __align__(16) float hs[32][RCH];
    __shared__ int cpos[RCH];

    int tid = threadIdx.x;
    int ct = tid & 31;
    int cg = tid >> 5;
    int n0 = nt * 128;
    float bv[4];
#pragma unroll
    for (int q = 0; q < 4; q++) bv[q] = bias[n0 + ct + 32 * q];

    for (int c0 = zc * RCH; c0 < C; c0 += RZ * RCH) {
        int nc = C - c0;
        if (nc > RCH) nc = RCH;
        __syncthreads();
        if (tid < nc) cpos[tid] = g_cand[b * MAXC + c0 + tid];

        float acc[4][8];
#pragma unroll
        for (int q = 0; q < 4; q++)
#pragma unroll
            for (int j = 0; j < 8; j++) acc[q][j] = 0.0f;

        bool active = (cg * 8 < nc);

        for (int kt = 0; kt < 32; kt++) {
            __syncthreads();
            for (int i = tid; i < 4096; i += 256) {
                int kk = i >> 7, nn = i & 127;
                Ws[kk][nn] = W[(size_t)(kt * 32 + kk) * HDIM + n0 + nn];
            }
            for (int i = tid; i < 32 * RCH; i += 256) {
                int kk = i >> 6, c = i & 63;
                hs[kk][c] = (c < nc)
                    ? hid[(size_t)(b * SDIM + cpos[c]) * HDIM + kt * 32 + kk]
                    : 0.0f;
            }
            __syncthreads();
            if (active) {
#pragma unroll 4
                for (int kk = 0; kk < 32; kk++) {
                    float w0 = Ws[kk][ct], w1 = Ws[kk][ct + 32];
                    float w2 = Ws[kk][ct + 64], w3 = Ws[kk][ct + 96];
                    float4 ha = *(const float4*)&hs[kk][cg * 8];
                    float4 hb = *(const float4*)&hs[kk][cg * 8 + 4];
                    float h[8] = {ha.x, ha.y, ha.z, ha.w, hb.x, hb.y, hb.z, hb.w};
#pragma unroll
                    for (int j = 0; j < 8; j++) {
                        acc[0][j] += w0 * h[j];
                        acc[1][j] += w1 * h[j];
                        acc[2][j] += w2 * h[j];
                        acc[3][j] += w3 * h[j];
                    }
                }
            }
        }
        if (active) {
#pragma unroll
            for (int j = 0; j < 8; j++) {
                float v = fmaxf(fmaxf(acc[0][j] + bv[0], acc[1][j] + bv[1]),
                                fmaxf(acc[2][j] + bv[2], acc[3][j] + bv[3]));
#pragma unroll
                for (int off = 16; off > 0; off >>= 1)
                    v = fmaxf(v, __shfl_xor_sync(0xFFFFFFFFu, v, off));
                int c = cg * 8 + j;
                if (ct == 0 && c < nc)
                    atomicMax(&g_exact[b * SDIM + cpos[c]], mono(v));
            }
        }
    }
}

// ---------------------------------------------------------------------------
// K5: final classification -> mask (runtime-sized candidate sort)
// ---------------------------------------------------------------------------
__global__ void select2_kernel(const float* __restrict__ pmask,
                               const float* __restrict__ amask,
                               float* __restrict__ outmask) {
    int b = blockIdx.x, t = threadIdx.x;
    __shared__ unsigned long long ck[MAXC];
    __shared__ int cnt[1024];
    __shared__ unsigned long long cthrS;
    int base = b * SDIM;
    float thr = g_thrA[b];
    int C = g_ccount[b];
    if (C > MAXC) C = MAXC;

    int psize = 1;
    while (psize < C) psize <<= 1;
    if (psize < 2) psize = 2;

    int local = 0;
#pragma unroll
    for (int r = 0; r < 4; r++) {
        int i = t * 4 + r;
        if (pmask[base + i] > 0.5f && make_score(base, i, amask) > thr + WND) local++;
    }
    cnt[t] = local;

    if (t < psize) {
        unsigned long long myk = 0ull;
        if (t < C) {
            int pos = g_cand[b * MAXC + t];
            myk = ((unsigned long long)g_exact[base + pos] << 32) |
                  (unsigned long long)(0xFFFFFFFFu - (unsigned)pos);
        }
        ck[t] = myk;
    }
    __syncthreads();

    for (int off = 512; off > 0; off >>= 1) {
        if (t < off) cnt[t] += cnt[t + off];
        __syncthreads();
    }
    int D = cnt[0];

    for (int k = 2; k <= psize; k <<= 1)
        for (int j = k >> 1; j > 0; j >>= 1) {
            int ixj = t ^ j;
            if (t < psize && ixj > t) {
                unsigned long long A = ck[t], B = ck[ixj];
                bool up = ((t & k) == 0);
                if ((A > B) == up) { ck[t] = B; ck[ixj] = A; }
            }
            __syncthreads();
        }

    if (t == 0) {
        int T = (int)((float)g_nzero[b] * 0.8f);
        if (T < 1) T = 1;
        int r = T - D;
        if (r < 1) cthrS = ~0ull;
        else {
            if (r > C) r = C;
            cthrS = ck[psize - r];
        }
    }
    __syncthreads();
    unsigned long long cthr = cthrS;

#pragma unroll
    for (int r = 0; r < 4; r++) {
        int i = t * 4 + r;
        float out = 0.0f;
        if (pmask[base + i] > 0.5f) {
            float sc = make_score(base, i, amask);
            if (sc > thr + WND) out = 1.0f;
            else if (fabsf(sc - thr) <= WND) {
                unsigned long long k = ((unsigned long long)g_exact[base + i] << 32) |
                                       (unsigned long long)(0xFFFFFFFFu - (unsigned)i);
                if (k >= cthr) out = 1.0f;
            }
        }
        outmask[base + i] = out;
    }
}

// ---------------------------------------------------------------------------
extern "C" void kernel_launch(void* const* d_in, const int* in_sizes, int n_in,
                              void* d_out, int out_size) {
    const float* hidden = (const float*)d_in[0];
    const float* amask  = (const float*)d_in[1];
    const float* pmask  = (const float*)d_in[2];
    const float* W      = (const float*)d_in[3];
    const float* bias   = (const float*)d_in[4];
    float* out = (float*)d_out;

    const int nh = BDIM * SDIM * HDIM;
    float* out_ret  = out;
    float* out_mask = out + nh;

    cudaFuncSetAttribute(score_gemm, cudaFuncAttributeMaxDynamicSharedMemorySize, SMEM_DYN);

    compact_kernel<<<BDIM, 1024>>>(pmask, amask);
    prep_w<<<dim3(32, 32), dim3(32, 8)>>>(W);
    prep_copy<<<BDIM * SDIM, 128>>>((const float4*)hidden, (float4*)out_ret);
    score_gemm<<<dim3(SDIM / BM, HDIM / BN, BDIM), 256, SMEM_DYN>>>(bias);
    select1_kernel<<<BDIM, 1024>>>(pmask, amask);
    rescore_kernel<<<dim3(8, BDIM, RZ), 256>>>(hidden, W, bias);
    select2_kernel<<<BDIM, 1024>>>(pmask, amask, out_mask);
}